// round 5
// baseline (speedup 1.0000x reference)
#include <cuda_runtime.h>
#include <math.h>

#define Bsz 128
#define Tsz 1024
#define Fsz 128
#define Hsz 256
#define KC  32
#define NTHR 128
#define TLAST 1020

// Persistent state
__device__ float g_h[3][2][Bsz][Hsz];   // double-buffered hidden state per layer
__device__ float g_c[3][Bsz][Hsz];      // cell state
__device__ unsigned g_cnt[8][32];       // per-group barrier counters (128B padded)
__device__ volatile unsigned g_gen[8][32];

struct SmemT {
    float w[2][KC][4][16];   // [buf][k][gate][j]   8KB x2
    float in[2][KC][16];     // [buf][k][b]         2KB x2
};

__device__ __forceinline__ float sigmoidf_(float x) { return 1.f / (1.f + expf(-x)); }

// 16-block group barrier (blocks sharing one batch slice)
__device__ __forceinline__ void group_sync(int bg, unsigned &gen) {
    __syncthreads();
    if (threadIdx.x == 0) {
        gen++;
        __threadfence();   // drain this CTA's stores to L2 before arriving
        unsigned old = atomicAdd(&g_cnt[bg][0], 1u);
        if (old == 15u) {
            g_cnt[bg][0] = 0u;
            __threadfence();
            atomicExch((unsigned*)&g_gen[bg][0], gen);
        } else {
            while (g_gen[bg][0] != gen) { }
        }
        __threadfence();   // acquire: invalidate L1 so post-barrier reads are fresh
    }
    __syncthreads();
}

__device__ __forceinline__ void store_w(SmemT* s, int buf, int wh, int wg, int wj,
                                        const float4* wv) {
#pragma unroll
    for (int q = 0; q < 4; q++) {
        s->w[buf][wh + q*4 + 0][wg][wj] = wv[q].x;
        s->w[buf][wh + q*4 + 1][wg][wj] = wv[q].y;
        s->w[buf][wh + q*4 + 2][wg][wj] = wv[q].z;
        s->w[buf][wh + q*4 + 3][wg][wj] = wv[q].w;
    }
}

// One GEMM segment: acc += inp[b, :K] * W[n, :K]^T, streamed in KC chunks,
// double-buffered through smem. Thread k-splits 4 ways (ks = tid&3).
__device__ __forceinline__ void do_segment(SmemT* s,
    const float* __restrict__ W, int K,
    const float* __restrict__ inp, long strideB,
    int jbase, int bbase, int ks, int bq, int jp,
    float acc[2][4][4])
{
    const int tid = threadIdx.x;
    const int wg = tid >> 5;            // gate 0..3
    const int wj = (tid >> 1) & 15;     // j within tile
    const int wh = (tid & 1) << 4;      // k half offset 0/16
    const int sb = tid >> 3;            // batch row for input staging
    const int sq = tid & 7;             // k quad for input staging
    const float* wrow = W + (size_t)(wg * Hsz + jbase + wj) * K + wh;
    const float* irow = inp + (size_t)(bbase + sb) * strideB + sq * 4;
    const int nchunk = K / KC;          // 4, 8 — always even

    float4 wv[4]; float4 iv;
#pragma unroll
    for (int q = 0; q < 4; q++) wv[q] = __ldcg((const float4*)(wrow + q*4));
    iv = __ldcg((const float4*)irow);
    store_w(s, 0, wh, wg, wj, wv);
    s->in[0][sq*4+0][sb] = iv.x;
    s->in[0][sq*4+1][sb] = iv.y;
    s->in[0][sq*4+2][sb] = iv.z;
    s->in[0][sq*4+3][sb] = iv.w;
    __syncthreads();

    for (int ci = 0; ci < nchunk; ci++) {
        const int cur = ci & 1;
        const int nxt = cur ^ 1;
        const bool more = (ci + 1 < nchunk);
        if (more) {
            const int k0 = (ci + 1) * KC;
#pragma unroll
            for (int q = 0; q < 4; q++) wv[q] = __ldcg((const float4*)(wrow + k0 + q*4));
            iv = __ldcg((const float4*)(irow + k0));
        }
#pragma unroll
        for (int k8 = 0; k8 < 8; k8++) {
            const int k = k8*4 + ks;
            const float4 xv = *(const float4*)&s->in[cur][k][bq*4];
#pragma unroll
            for (int g = 0; g < 4; g++) {
                const float2 ww = *(const float2*)&s->w[cur][k][g][jp*2];
                acc[0][g][0] = fmaf(ww.x, xv.x, acc[0][g][0]);
                acc[0][g][1] = fmaf(ww.x, xv.y, acc[0][g][1]);
                acc[0][g][2] = fmaf(ww.x, xv.z, acc[0][g][2]);
                acc[0][g][3] = fmaf(ww.x, xv.w, acc[0][g][3]);
                acc[1][g][0] = fmaf(ww.y, xv.x, acc[1][g][0]);
                acc[1][g][1] = fmaf(ww.y, xv.y, acc[1][g][1]);
                acc[1][g][2] = fmaf(ww.y, xv.z, acc[1][g][2]);
                acc[1][g][3] = fmaf(ww.y, xv.w, acc[1][g][3]);
            }
        }
        if (more) {
            // buf[nxt] last read before previous iteration's __syncthreads
            store_w(s, nxt, wh, wg, wj, wv);
            s->in[nxt][sq*4+0][sb] = iv.x;
            s->in[nxt][sq*4+1][sb] = iv.y;
            s->in[nxt][sq*4+2][sb] = iv.z;
            s->in[nxt][sq*4+3][sb] = iv.w;
        }
        __syncthreads();
    }
}

__device__ __forceinline__ void layer_update(SmemT* s,
    const float* __restrict__ WA, int KA, const float* __restrict__ inpA, long strideA,
    const float* __restrict__ WB, const float* __restrict__ inpB,
    const float* __restrict__ bih, const float* __restrict__ bhh,
    float* __restrict__ cbase, float* __restrict__ hout,
    float* __restrict__ yout, int t0,
    int jbase, int bbase)
{
    const int tid = threadIdx.x;
    const int ks  = tid & 3;        // k-split lane
    const int pos = tid >> 2;
    const int bq  = pos & 3;        // batch quad
    const int jp  = pos >> 2;       // j pair

    float acc[2][4][4];
#pragma unroll
    for (int p = 0; p < 2; p++)
#pragma unroll
        for (int g = 0; g < 4; g++)
#pragma unroll
            for (int u = 0; u < 4; u++) acc[p][g][u] = 0.f;

    do_segment(s, WA, KA,  inpA, strideA, jbase, bbase, ks, bq, jp, acc);
    do_segment(s, WB, Hsz, inpB, Hsz,     jbase, bbase, ks, bq, jp, acc);

    // reduce the 4-way k-split across adjacent lanes (ks = lane&3)
#pragma unroll
    for (int p = 0; p < 2; p++)
#pragma unroll
        for (int g = 0; g < 4; g++)
#pragma unroll
            for (int u = 0; u < 4; u++) {
                float v = acc[p][g][u];
                v += __shfl_xor_sync(0xffffffffu, v, 1);
                v += __shfl_xor_sync(0xffffffffu, v, 2);
                acc[p][g][u] = v;
            }

    // each lane handles batch u == ks; select with SELs (no dynamic reg indexing)
    const int j0 = jbase + jp * 2;
    const int b  = bbase + bq * 4 + ks;
#pragma unroll
    for (int p = 0; p < 2; p++) {
        float gv[4];
#pragma unroll
        for (int g = 0; g < 4; g++) {
            float v = acc[p][g][0];
            if (ks == 1) v = acc[p][g][1];
            if (ks == 2) v = acc[p][g][2];
            if (ks == 3) v = acc[p][g][3];
            gv[g] = v;
        }
        const int j = j0 + p;
        const float gi = gv[0] + bih[j]           + bhh[j];
        const float gf = gv[1] + bih[Hsz + j]     + bhh[Hsz + j];
        const float gg = gv[2] + bih[2*Hsz + j]   + bhh[2*Hsz + j];
        const float go = gv[3] + bih[3*Hsz + j]   + bhh[3*Hsz + j];
        const float i_ = sigmoidf_(gi);
        const float f_ = sigmoidf_(gf);
        const float g_ = tanhf(gg);
        const float o_ = sigmoidf_(go);
        const float cn = f_ * cbase[b*Hsz + j] + i_ * g_;
        const float hn = o_ * tanhf(cn);
        cbase[b*Hsz + j] = cn;
        hout[b*Hsz + j]  = hn;
        if (yout) {
#pragma unroll
            for (int u = 0; u < 4; u++)
                yout[((size_t)b * Tsz + (t0 + u)) * Hsz + j] = hn;
        }
    }
}

__global__ void __launch_bounds__(NTHR, 1) drnn_persistent(
    const float* __restrict__ x,
    const float* __restrict__ Wih0, const float* __restrict__ Whh0,
    const float* __restrict__ bih0, const float* __restrict__ bhh0,
    const float* __restrict__ Wih1, const float* __restrict__ Whh1,
    const float* __restrict__ bih1, const float* __restrict__ bhh1,
    const float* __restrict__ Wih2, const float* __restrict__ Whh2,
    const float* __restrict__ bih2, const float* __restrict__ bhh2,
    float* __restrict__ y)
{
    __shared__ SmemT s;
    const int bid = blockIdx.x;
    const int jg = bid & 15;       // 16 j-slices
    const int bg = bid >> 4;       // 8 independent batch groups
    const int jbase = jg * 16;
    const int bbase = bg * 16;
    const int tid = threadIdx.x;

    unsigned gen = 0;
    if (jg == 0 && tid == 0) g_gen[bg][0] = 0;   // reset before first arrive (fenced in sync)

    // zero this block's state slices (covers everything across the group)
    for (int i = tid; i < 256; i += NTHR) {
        const int jj = jbase + (i & 15);
        const int bb = bbase + (i >> 4);
#pragma unroll
        for (int l = 0; l < 3; l++) {
            g_h[l][0][bb][jj] = 0.f;
            g_h[l][1][bb][jj] = 0.f;
            g_c[l][bb][jj]    = 0.f;
        }
    }
    group_sync(bg, gen);

    int p0 = 0, p1 = 0, p2 = 0;
    for (int t = 0; t <= TLAST; t++) {
        // layer 0 — every step
        layer_update(&s, Wih0, Fsz, x + (size_t)t * Fsz, (long)Tsz * Fsz,
                     Whh0, &g_h[0][p0][0][0], bih0, bhh0,
                     &g_c[0][0][0], &g_h[0][p0 ^ 1][0][0], nullptr, 0,
                     jbase, bbase);
        p0 ^= 1;
        group_sync(bg, gen);

        if ((t & 1) == 0) {
            // layer 1 — every 2nd step; reads h0 just written
            layer_update(&s, Wih1, Hsz, &g_h[0][p0][0][0], Hsz,
                         Whh1, &g_h[1][p1][0][0], bih1, bhh1,
                         &g_c[1][0][0], &g_h[1][p1 ^ 1][0][0], nullptr, 0,
                         jbase, bbase);
            p1 ^= 1;
            if ((t & 3) == 0) {
                group_sync(bg, gen);   // layer2 consumes h1 immediately
                layer_update(&s, Wih2, Hsz, &g_h[1][p1][0][0], Hsz,
                             Whh2, &g_h[2][p2][0][0], bih2, bhh2,
                             &g_c[2][0][0], &g_h[2][p2 ^ 1][0][0], y, t,
                             jbase, bbase);
                p2 ^= 1;
            }
            // no barrier needed here: next consumers are separated by the
            // barrier after the following layer-0 update
        }
    }
}

extern "C" void kernel_launch(void* const* d_in, const int* in_sizes, int n_in,
                              void* d_out, int out_size) {
    const float* x    = (const float*)d_in[0];
    const float* Wih0 = (const float*)d_in[1];
    const float* Whh0 = (const float*)d_in[2];
    const float* bih0 = (const float*)d_in[3];
    const float* bhh0 = (const float*)d_in[4];
    const float* Wih1 = (const float*)d_in[5];
    const float* Whh1 = (const float*)d_in[6];
    const float* bih1 = (const float*)d_in[7];
    const float* bhh1 = (const float*)d_in[8];
    const float* Wih2 = (const float*)d_in[9];
    const float* Whh2 = (const float*)d_in[10];
    const float* bih2 = (const float*)d_in[11];
    const float* bhh2 = (const float*)d_in[12];
    float* y = (float*)d_out;

    drnn_persistent<<<128, NTHR>>>(x,
        Wih0, Whh0, bih0, bhh0,
        Wih1, Whh1, bih1, bhh1,
        Wih2, Whh2, bih2, bhh2, y);
}